// round 14
// baseline (speedup 1.0000x reference)
#include <cuda_runtime.h>

// ---------------------------------------------------------------------------
// Voxel2Point via occupancy-grid 3-NN (R14 = warp-cooperative window search):
//   - one warp per point: 32 lanes split the 121 rows of an 11^3 Chebyshev
//     window (radius 5) around the point's cell; packed (d2,idx) u64 keys;
//     3-round warp min-reduce for the exact top-3 (== stable jax top_k)
//   - success iff D2 + 1e-6 < ((6-0.5)*unit)^2: provably identical to the
//     scalar expanding-shell result; ~0.1% of points fail -> lane-0 scalar
//     fallback (full shell loop + 4D cross-batch rescan), bit-exact
//   - direct-mapped g_cell (one LDG.128 per candidate), smem bitmask,
//     points spatially sorted by (batch, cz, cy, cx>>4)
// ---------------------------------------------------------------------------

#define NB     4
#define M_MAX  16384
#define N_MAX  131072
#define TPB    512
#define BPTS   512
#define MAXBLK (N_MAX / BPTS + NB)
#define BIGF   1e30f
#define CELLS  262144          // 64^3
#define BMW    8192            // bitmask words per batch (64^3 / 32)
#define BUK    65536           // sort buckets: (b, cz, cy, cx>>4)
#define NPART  256             // scan partitions (BUK / 256)
#define CHAINF 0x40000000      // "cell has more entries" flag in g_cell.w
#define IDXM   0x3FFF          // index mask (M <= 16384)
#define W      5               // window Chebyshev radius
#define WD     11              // 2W+1
#define WROWS  121             // WD*WD
#define BR2    0.075625f       // ((W+1) - 0.5)^2 * unit^2, unit = 0.05
#define MAXK   0xFFFFFFFFFFFFFFFFull

typedef unsigned long long ull;

__device__ int    g_head[NB * CELLS];
__device__ float4 g_qpos[M_MAX];      // x,y,z = center; w = next index bits
__device__ float4 g_cell[NB * CELLS]; // head entry — bitmask-guarded, no init
__device__ unsigned int g_bm[NB * BMW];
__device__ int    g_bcnt[BUK];
__device__ int    g_bcur[BUK];
__device__ int    g_part[NPART];
__device__ int    g_pid[N_MAX];
__device__ int    g_nblk;
__device__ int    g_dstart[MAXBLK];
__device__ int    g_dend[MAXBLK];
__device__ int    g_dbatch[MAXBLK];
__device__ int4   g_iw[N_MAX];        // packed neighbor indices (i0,i1,i2,0)
__device__ float4 g_wv[N_MAX];        // packed weights (w0,w1,w2,0)

// ---- init ----
__global__ void k_init() {
    int i = blockIdx.x * blockDim.x + threadIdx.x;
    int stride = gridDim.x * blockDim.x;
    for (int k = i; k < NB * CELLS; k += stride) g_head[k] = -1;
    for (int k = i; k < NB * BMW; k += stride) g_bm[k] = 0u;
    for (int k = i; k < BUK; k += stride) g_bcnt[k] = 0;
}

__device__ __forceinline__ int cell_of(float v) {
    return min(63, max(0, (int)floorf(fmaf(v, 20.0f, 32.0f))));
}
__device__ __forceinline__ int key_of(int b, const float* pc, int i) {
    int cx = cell_of(pc[3 * i]);
    int cy = cell_of(pc[3 * i + 1]);
    int cz = cell_of(pc[3 * i + 2]);
    return (b << 14) | (cz << 8) | (cy << 2) | (cx >> 4);
}

// ---- fused: voxel build (i < M) + point histogram (i < N) ----
__global__ void k_build_hist(const int* __restrict__ indices, int M,
                             const float* __restrict__ pc,
                             const int* __restrict__ bids, int N) {
    int i = blockIdx.x * blockDim.x + threadIdx.x;
    if (i < M) {
        int4 v = ((const int4*)indices)[i];
        // replicate reference rounding: mul, add, add as separate ops (no FMA)
        float qx = __fadd_rn(__fadd_rn(__fmul_rn((float)v.y, 0.05f), -1.6f), 0.025f);
        float qy = __fadd_rn(__fadd_rn(__fmul_rn((float)v.z, 0.05f), -1.6f), 0.025f);
        float qz = __fadd_rn(__fadd_rn(__fmul_rn((float)v.w, 0.05f), -1.6f), 0.025f);
        int cell = (((v.w << 6) | v.z) << 6) | v.y;   // X fastest
        int old = atomicExch(&g_head[v.x * CELLS + cell], i);
        g_qpos[i] = make_float4(qx, qy, qz, __int_as_float(old));
        atomicOr(&g_bm[v.x * BMW + (cell >> 5)], 1u << (cell & 31));
    }
    if (i < N) atomicAdd(&g_bcnt[key_of(bids[i], pc, i)], 1);
}

// ---- fused: partition sums (blocks [0,NPART)) + cell compact (rest) ----
__global__ void __launch_bounds__(256) k_part_compact(const int* __restrict__ indices, int M) {
    if (blockIdx.x < NPART) {
        __shared__ int s[256];
        int t = threadIdx.x;
        s[t] = g_bcnt[blockIdx.x * 256 + t];
        __syncthreads();
        for (int o = 128; o > 0; o >>= 1) {
            if (t < o) s[t] += s[t + o];
            __syncthreads();
        }
        if (t == 0) g_part[blockIdx.x] = s[0];
    } else {
        int i = (blockIdx.x - NPART) * 256 + threadIdx.x;
        if (i >= M) return;
        int4 v = ((const int4*)indices)[i];
        int cell = (((v.w << 6) | v.z) << 6) | v.y;
        int slot = v.x * CELLS + cell;
        if (g_head[slot] == i) {
            float4 q = g_qpos[i];
            int next = __float_as_int(q.w);
            int wbits = i | (next >= 0 ? CHAINF : 0);
            g_cell[slot] = make_float4(q.x, q.y, q.z, __int_as_float(wbits));
        }
    }
}

// ---- fused top+off ----
__global__ void __launch_bounds__(256) k_off2() {
    __shared__ int ps[256];
    __shared__ int s[256];
    int t = threadIdx.x;

    ps[t] = g_part[t];
    __syncthreads();
    for (int o = 1; o < 256; o <<= 1) {
        int v = (t >= o) ? ps[t - o] : 0;
        __syncthreads();
        ps[t] += v;
        __syncthreads();
    }
    int mybase = (blockIdx.x == 0) ? 0 : ps[blockIdx.x - 1];

    int base = blockIdx.x * 256;
    int v0 = g_bcnt[base + t];
    s[t] = v0;
    __syncthreads();
    for (int o = 1; o < 256; o <<= 1) {
        int v = (t >= o) ? s[t - o] : 0;
        __syncthreads();
        s[t] += v;
        __syncthreads();
    }
    g_bcur[base + t] = mybase + s[t] - v0;

    if (blockIdx.x == 0 && t == 0) {
        int dt = 0;
        for (int b = 0; b < NB; b++) {
            int cbase = (b == 0) ? 0 : ps[b * 64 - 1];
            int cend  = ps[(b + 1) * 64 - 1];
            for (int k = cbase; k < cend; k += BPTS) {
                g_dstart[dt] = k;
                g_dend[dt]   = min(cend, k + BPTS);
                g_dbatch[dt] = b;
                dt++;
            }
        }
        g_nblk = dt;
    }
}

__global__ void k_scatterp(const float* __restrict__ pc, const int* __restrict__ bids, int N) {
    int i = blockIdx.x * blockDim.x + threadIdx.x;
    if (i < N) {
        int pos = atomicAdd(&g_bcur[key_of(bids[i], pc, i)], 1);
        g_pid[pos] = i;
    }
}

// scalar-path insert (d, idx) lexicographic == stable jax top_k
#define INS3(dd, e)                                                          \
    do {                                                                     \
        float _d = (dd); int _e = (e);                                       \
        if (_d < D2 || (_d == D2 && _e < I2)) {                              \
            if (_d < D1 || (_d == D1 && _e < I1)) {                          \
                if (_d < D0 || (_d == D0 && _e < I0)) {                      \
                    D2 = D1; I2 = I1; D1 = D0; I1 = I0; D0 = _d; I0 = _e;    \
                } else { D2 = D1; I2 = I1; D1 = _d; I1 = _e; }               \
            } else { D2 = _d; I2 = _e; }                                     \
        }                                                                    \
    } while (0)

#define PROW(zz, yy, mk)                                                     \
    do {                                                                     \
        ull rowm =                                                           \
            *(const ull*)&sbm[((((zz) << 6) + (yy)) << 1)];                  \
        rowm &= (mk);                                                        \
        while (rowm) {                                                       \
            int xb = __ffsll((long long)rowm) - 1;                           \
            rowm &= rowm - 1;                                                \
            int cell = (((((zz) << 6) + (yy)) << 6) + xb);                   \
            float4 qq = g_cell[hb + cell];                                   \
            int wi = __float_as_int(qq.w);                                   \
            int qi = wi & IDXM;                                              \
            float ddx = px - qq.x, ddy = py - qq.y, ddz = pz - qq.z;         \
            float dd = fmaf(ddx, ddx, fmaf(ddy, ddy, ddz * ddz));            \
            INS3(dd, qi);                                                    \
            if (wi & CHAINF) {                                               \
                int e = __float_as_int(g_qpos[qi].w);                        \
                while (e >= 0) {                                             \
                    float4 q2 = g_qpos[e];                                   \
                    float ex = px - q2.x, ey = py - q2.y, ez = pz - q2.z;    \
                    float d2c = fmaf(ex, ex, fmaf(ey, ey, ez * ez));         \
                    INS3(d2c, e);                                            \
                    e = __float_as_int(q2.w);                                \
                }                                                            \
            }                                                                \
        }                                                                    \
    } while (0)

// full scalar search (R13 logic), used for rare window failures
__device__ void scalar_point(const unsigned int* sbm, int hb, int b,
                             float px, float py, float pz,
                             const int* __restrict__ indices, int M, int pid) {
    int cx = cell_of(px);
    int cy = cell_of(py);
    int cz = cell_of(pz);

    float D0 = BIGF, D1 = BIGF, D2 = BIGF;
    int   I0 = 0,    I1 = 0,    I2 = 0;

    for (int r = 0; r <= 63; r++) {
        if (r > 0 && D2 < BIGF) {
            float br = ((float)r - 0.5f) * 0.05f;
            if (D2 + 1e-6f < br * br) break;
        }
        if (r == 0) {
            PROW(cz, cy, 1ull << cx);
            continue;
        }
        int xlo = max(cx - r, 0), xhi = min(cx + r, 63);
        ull fm = (xhi - xlo == 63) ? ~0ull
                                   : (((1ull << (xhi - xlo + 1)) - 1ull) << xlo);
        ull pm = 0ull;
        if (cx - r >= 0)  pm |= 1ull << (cx - r);
        if (cx + r <= 63) pm |= 1ull << (cx + r);

        int ylo = max(cy - r, 0), yhi = min(cy + r, 63);
        if (cz - r >= 0)  { int z = cz - r; for (int y = ylo; y <= yhi; y++) PROW(z, y, fm); }
        if (cz + r <= 63) { int z = cz + r; for (int y = ylo; y <= yhi; y++) PROW(z, y, fm); }
        int z0 = max(cz - r + 1, 0), z1 = min(cz + r - 1, 63);
        if (cy - r >= 0)  { int y = cy - r; for (int z = z0; z <= z1; z++) PROW(z, y, fm); }
        if (cy + r <= 63) { int y = cy + r; for (int z = z0; z <= z1; z++) PROW(z, y, fm); }
        if (pm) {
            int y0 = max(cy - r + 1, 0), y1 = min(cy + r - 1, 63);
            for (int z = z0; z <= z1; z++)
                for (int y = y0; y <= y1; y++) PROW(z, y, pm);
        }
    }

    if (D2 >= 1.0f) {   // cross-batch possible only here
        float pb = (float)b;
        D0 = BIGF; D1 = BIGF; D2 = BIGF; I0 = 0; I1 = 0; I2 = 0;
        for (int i = 0; i < M; i++) {
            int4 v = ((const int4*)indices)[i];
            float qb = (float)v.x;
            float qx = __fadd_rn(__fadd_rn(__fmul_rn((float)v.y, 0.05f), -1.6f), 0.025f);
            float qy = __fadd_rn(__fadd_rn(__fmul_rn((float)v.z, 0.05f), -1.6f), 0.025f);
            float qz = __fadd_rn(__fadd_rn(__fmul_rn((float)v.w, 0.05f), -1.6f), 0.025f);
            float dx = px - qx, dy = py - qy, dz = pz - qz, db = pb - qb;
            float dd = fmaf(dx, dx, fmaf(dy, dy, fmaf(dz, dz, db * db)));
            INS3(dd, i);
        }
    }

    float r0 = 1.0f / (D0 + 1e-8f);
    float r1 = 1.0f / (D1 + 1e-8f);
    float r2 = 1.0f / (D2 + 1e-8f);
    float s = r0 + r1 + r2;
    g_wv[pid] = make_float4(r0 / s, r1 / s, r2 / s, 0.0f);
    g_iw[pid] = make_int4(I0, I1, I2, 0);
}

// warp-local key insert (keys unique: idx in low bits)
#define KINS(kk)                                                             \
    do {                                                                     \
        ull _k = (kk);                                                       \
        if (_k < K2) {                                                       \
            if (_k < K1) {                                                   \
                if (_k < K0) { K2 = K1; K1 = K0; K0 = _k; }                  \
                else         { K2 = K1; K1 = _k; }                           \
            } else K2 = _k;                                                  \
        }                                                                    \
    } while (0)

#define WMIN(m)                                                              \
    do {                                                                     \
        for (int _o = 16; _o; _o >>= 1) {                                    \
            ull _v = __shfl_xor_sync(0xFFFFFFFFu, (m), _o);                  \
            if (_v < (m)) (m) = _v;                                          \
        }                                                                    \
    } while (0)

__global__ void __launch_bounds__(TPB) nn_kernel(const float* __restrict__ pc,
                                                 const int* __restrict__ indices,
                                                 int M) {
    __shared__ unsigned int sbm[BMW];
    if (blockIdx.x >= g_nblk) return;

    int b  = g_dbatch[blockIdx.x];
    int pS = g_dstart[blockIdx.x];
    int pE = g_dend[blockIdx.x];
    int hb = b * CELLS;

    {
        const uint4* src = (const uint4*)&g_bm[b * BMW];
        uint4* dst = (uint4*)sbm;
        for (int i = threadIdx.x; i < BMW / 4; i += TPB) dst[i] = src[i];
    }
    __syncthreads();

    int wid  = threadIdx.x >> 5;
    int lane = threadIdx.x & 31;
    const int NW = TPB / 32;

    for (int ni = pS + wid; ni < pE; ni += NW) {
        int pid = g_pid[ni];
        float px = pc[3 * pid], py = pc[3 * pid + 1], pz = pc[3 * pid + 2];

        int cx = cell_of(px);
        int cy = cell_of(py);
        int cz = cell_of(pz);

        int xlo = max(cx - W, 0), xhi = min(cx + W, 63);
        ull fm = ((1ull << (xhi - xlo + 1)) - 1ull) << xlo;   // width <= 11 < 64

        ull K0 = MAXK, K1 = MAXK, K2 = MAXK;

        // lanes split the 121 window rows
        for (int rr = lane; rr < WROWS; rr += 32) {
            int z = cz + rr / WD - W;
            int y = cy + rr % WD - W;
            if ((unsigned)z > 63u || (unsigned)y > 63u) continue;
            ull rowm = *(const ull*)&sbm[(((z << 6) + y) << 1)] & fm;
            while (rowm) {
                int xb = __ffsll((long long)rowm) - 1;
                rowm &= rowm - 1;
                int cell = (((z << 6) + y) << 6) + xb;
                float4 qq = g_cell[hb + cell];
                int wi = __float_as_int(qq.w);
                int qi = wi & IDXM;
                float dx = px - qq.x, dy = py - qq.y, dz = pz - qq.z;
                float dd = fmaf(dx, dx, fmaf(dy, dy, dz * dz));
                KINS(((ull)__float_as_uint(dd) << 32) | (unsigned)qi);
                if (wi & CHAINF) {
                    int e = __float_as_int(g_qpos[qi].w);
                    while (e >= 0) {
                        float4 q2 = g_qpos[e];
                        float ex = px - q2.x, ey = py - q2.y, ez = pz - q2.z;
                        float d2c = fmaf(ex, ex, fmaf(ey, ey, ez * ez));
                        KINS(((ull)__float_as_uint(d2c) << 32) | (unsigned)e);
                        e = __float_as_int(q2.w);
                    }
                }
            }
        }
        __syncwarp();

        // exact top-3 across the warp: 3 rounds of min-reduce with pop
        ull h0 = K0, h1 = K1, h2 = K2;
        ull R0 = h0; WMIN(R0); if (h0 == R0) { h0 = h1; h1 = h2; h2 = MAXK; }
        ull R1 = h0; WMIN(R1); if (h0 == R1) { h0 = h1; h1 = h2; h2 = MAXK; }
        ull R2 = h0; WMIN(R2);

        bool done = false;
        float D2v = BIGF;
        if (R2 != MAXK) {
            D2v = __uint_as_float((unsigned)(R2 >> 32));
            if (D2v + 1e-6f < BR2) done = true;   // bound at radius W+1; also < 1.0
        }

        if (done) {
            if (lane == 0) {
                float D0v = __uint_as_float((unsigned)(R0 >> 32));
                float D1v = __uint_as_float((unsigned)(R1 >> 32));
                float r0 = 1.0f / (D0v + 1e-8f);
                float r1 = 1.0f / (D1v + 1e-8f);
                float r2 = 1.0f / (D2v + 1e-8f);
                float s = r0 + r1 + r2;
                g_wv[pid] = make_float4(r0 / s, r1 / s, r2 / s, 0.0f);
                g_iw[pid] = make_int4((int)(R0 & 0xFFFFFFFFull),
                                      (int)(R1 & 0xFFFFFFFFull),
                                      (int)(R2 & 0xFFFFFFFFull), 0);
            }
        } else {
            if (lane == 0) scalar_point(sbm, hb, b, px, py, pz, indices, M, pid);
        }
    }
}

// ---- weighted gather-interpolate: 8 threads/point, 2 float4 chains each ----
__global__ void interp_kernel(const float* __restrict__ feats,
                              float* __restrict__ out, int N, int C) {
    int t = blockIdx.x * blockDim.x + threadIdx.x;
    int n = t >> 3;
    int c = t & 7;
    if (n >= N) return;

    int4   iv = g_iw[n];
    float4 wv = g_wv[n];
    const float4* f = (const float4*)feats;
    int C4 = C >> 2;           // 16
    long ba = (long)iv.x * C4 + c;
    long bb = (long)iv.y * C4 + c;
    long bc = (long)iv.z * C4 + c;

    float4 a0 = f[ba],     b0 = f[bb],     c0 = f[bc];
    float4 a1 = f[ba + 8], b1 = f[bb + 8], c1 = f[bc + 8];

    float4 o0, o1;
    o0.x = wv.x * a0.x + wv.y * b0.x + wv.z * c0.x;
    o0.y = wv.x * a0.y + wv.y * b0.y + wv.z * c0.y;
    o0.z = wv.x * a0.z + wv.y * b0.z + wv.z * c0.z;
    o0.w = wv.x * a0.w + wv.y * b0.w + wv.z * c0.w;
    o1.x = wv.x * a1.x + wv.y * b1.x + wv.z * c1.x;
    o1.y = wv.x * a1.y + wv.y * b1.y + wv.z * c1.y;
    o1.z = wv.x * a1.z + wv.y * b1.z + wv.z * c1.z;
    o1.w = wv.x * a1.w + wv.y * b1.w + wv.z * c1.w;

    float4* ov = (float4*)out;
    ov[(long)n * C4 + c]     = o0;
    ov[(long)n * C4 + c + 8] = o1;
}

extern "C" void kernel_launch(void* const* d_in, const int* in_sizes, int n_in,
                              void* d_out, int out_size) {
    const float* features = (const float*)d_in[0];  // (M, C) f32
    const int*   indices  = (const int*)d_in[1];    // (M, 4) i32
    const float* pc       = (const float*)d_in[2];  // (N, 3) f32
    const int*   bids     = (const int*)d_in[3];    // (N,)   i32

    int M = in_sizes[1] / 4;
    int C = in_sizes[0] / M;
    int N = in_sizes[3];
    int mx = (M > N) ? M : N;

    k_init<<<1024, 256>>>();
    k_build_hist<<<(mx + 255) / 256, 256>>>(indices, M, pc, bids, N);
    k_part_compact<<<NPART + (M + 255) / 256, 256>>>(indices, M);
    k_off2<<<NPART, 256>>>();
    k_scatterp<<<(N + 255) / 256, 256>>>(pc, bids, N);

    int maxblk = (N + BPTS - 1) / BPTS + NB;
    nn_kernel<<<maxblk, TPB>>>(pc, indices, M);

    interp_kernel<<<(N * 8 + 255) / 256, 256>>>(features, (float*)d_out, N, C);
}

// round 15
// speedup vs baseline: 1.9043x; 1.9043x over previous
#include <cuda_runtime.h>

// ---------------------------------------------------------------------------
// Voxel2Point via occupancy-grid 3-NN (R15 = R11 + 2D-ring row sweep in nn):
//   - one thread per point (TPB=512, validated best layout)
//   - search: (dz,dy) rings s=0..6 outward, each row visited at most once
//     with full +-6 x-mask; per-row lower-bound prune; ring break as before
//   - complete iff early ring break or D2+1e-6 < (6.5*u)^2; else R11 scalar
//     shell fallback (incl. exact 4D cross-batch rescan) -> bit-exact
//   - direct-mapped g_cell, smem bitmask, spatial point sort, fused setup
// ---------------------------------------------------------------------------

#define NB     4
#define M_MAX  16384
#define N_MAX  131072
#define TPB    512
#define BPTS   512
#define MAXBLK (N_MAX / BPTS + NB)
#define BIGF   1e30f
#define CELLS  262144          // 64^3
#define BMW    8192            // bitmask words per batch (64^3 / 32)
#define BUK    65536           // sort buckets: (b, cz, cy, cx>>4)
#define NPART  256             // scan partitions (BUK / 256)
#define CHAINF 0x40000000      // "cell has more entries" flag in g_cell.w
#define IDXM   0x3FFF          // index mask (M <= 16384)
#define WR     6               // window radius for ring sweep
#define XBND2  0.105625f       // ((WR+1) - 0.5)^2 * u^2, u = 0.05

typedef unsigned long long ull;

__device__ int    g_head[NB * CELLS];
__device__ float4 g_qpos[M_MAX];      // x,y,z = center; w = next index bits
__device__ float4 g_cell[NB * CELLS]; // head entry — bitmask-guarded, no init
__device__ unsigned int g_bm[NB * BMW];
__device__ int    g_bcnt[BUK];
__device__ int    g_bcur[BUK];
__device__ int    g_part[NPART];
__device__ int    g_pid[N_MAX];
__device__ int    g_nblk;
__device__ int    g_dstart[MAXBLK];
__device__ int    g_dend[MAXBLK];
__device__ int    g_dbatch[MAXBLK];
__device__ int4   g_iw[N_MAX];
__device__ float4 g_wv[N_MAX];

// ---- init ----
__global__ void k_init() {
    int i = blockIdx.x * blockDim.x + threadIdx.x;
    int stride = gridDim.x * blockDim.x;
    for (int k = i; k < NB * CELLS; k += stride) g_head[k] = -1;
    for (int k = i; k < NB * BMW; k += stride) g_bm[k] = 0u;
    for (int k = i; k < BUK; k += stride) g_bcnt[k] = 0;
}

__device__ __forceinline__ int cell_of(float v) {
    return min(63, max(0, (int)floorf(fmaf(v, 20.0f, 32.0f))));
}
__device__ __forceinline__ int key_of(int b, const float* pc, int i) {
    int cx = cell_of(pc[3 * i]);
    int cy = cell_of(pc[3 * i + 1]);
    int cz = cell_of(pc[3 * i + 2]);
    return (b << 14) | (cz << 8) | (cy << 2) | (cx >> 4);
}

// ---- fused: voxel build (i < M) + point histogram (i < N) ----
__global__ void k_build_hist(const int* __restrict__ indices, int M,
                             const float* __restrict__ pc,
                             const int* __restrict__ bids, int N) {
    int i = blockIdx.x * blockDim.x + threadIdx.x;
    if (i < M) {
        int4 v = ((const int4*)indices)[i];
        // replicate reference rounding: mul, add, add as separate ops (no FMA)
        float qx = __fadd_rn(__fadd_rn(__fmul_rn((float)v.y, 0.05f), -1.6f), 0.025f);
        float qy = __fadd_rn(__fadd_rn(__fmul_rn((float)v.z, 0.05f), -1.6f), 0.025f);
        float qz = __fadd_rn(__fadd_rn(__fmul_rn((float)v.w, 0.05f), -1.6f), 0.025f);
        int cell = (((v.w << 6) | v.z) << 6) | v.y;   // X fastest
        int old = atomicExch(&g_head[v.x * CELLS + cell], i);
        g_qpos[i] = make_float4(qx, qy, qz, __int_as_float(old));
        atomicOr(&g_bm[v.x * BMW + (cell >> 5)], 1u << (cell & 31));
    }
    if (i < N) atomicAdd(&g_bcnt[key_of(bids[i], pc, i)], 1);
}

// ---- fused: partition sums + cell compact ----
__global__ void __launch_bounds__(256) k_part_compact(const int* __restrict__ indices, int M) {
    if (blockIdx.x < NPART) {
        __shared__ int s[256];
        int t = threadIdx.x;
        s[t] = g_bcnt[blockIdx.x * 256 + t];
        __syncthreads();
        for (int o = 128; o > 0; o >>= 1) {
            if (t < o) s[t] += s[t + o];
            __syncthreads();
        }
        if (t == 0) g_part[blockIdx.x] = s[0];
    } else {
        int i = (blockIdx.x - NPART) * 256 + threadIdx.x;
        if (i >= M) return;
        int4 v = ((const int4*)indices)[i];
        int cell = (((v.w << 6) | v.z) << 6) | v.y;
        int slot = v.x * CELLS + cell;
        if (g_head[slot] == i) {
            float4 q = g_qpos[i];
            int next = __float_as_int(q.w);
            int wbits = i | (next >= 0 ? CHAINF : 0);
            g_cell[slot] = make_float4(q.x, q.y, q.z, __int_as_float(wbits));
        }
    }
}

// ---- fused top+off ----
__global__ void __launch_bounds__(256) k_off2() {
    __shared__ int ps[256];
    __shared__ int s[256];
    int t = threadIdx.x;

    ps[t] = g_part[t];
    __syncthreads();
    for (int o = 1; o < 256; o <<= 1) {
        int v = (t >= o) ? ps[t - o] : 0;
        __syncthreads();
        ps[t] += v;
        __syncthreads();
    }
    int mybase = (blockIdx.x == 0) ? 0 : ps[blockIdx.x - 1];

    int base = blockIdx.x * 256;
    int v0 = g_bcnt[base + t];
    s[t] = v0;
    __syncthreads();
    for (int o = 1; o < 256; o <<= 1) {
        int v = (t >= o) ? s[t - o] : 0;
        __syncthreads();
        s[t] += v;
        __syncthreads();
    }
    g_bcur[base + t] = mybase + s[t] - v0;

    if (blockIdx.x == 0 && t == 0) {
        int dt = 0;
        for (int b = 0; b < NB; b++) {
            int cbase = (b == 0) ? 0 : ps[b * 64 - 1];
            int cend  = ps[(b + 1) * 64 - 1];
            for (int k = cbase; k < cend; k += BPTS) {
                g_dstart[dt] = k;
                g_dend[dt]   = min(cend, k + BPTS);
                g_dbatch[dt] = b;
                dt++;
            }
        }
        g_nblk = dt;
    }
}

__global__ void k_scatterp(const float* __restrict__ pc, const int* __restrict__ bids, int N) {
    int i = blockIdx.x * blockDim.x + threadIdx.x;
    if (i < N) {
        int pos = atomicAdd(&g_bcur[key_of(bids[i], pc, i)], 1);
        g_pid[pos] = i;
    }
}

// tie-aware top-3 insert: (d, idx) lexicographic, matches stable jax top_k
#define INS3(dd, e)                                                          \
    do {                                                                     \
        float _d = (dd); int _e = (e);                                       \
        if (_d < D2 || (_d == D2 && _e < I2)) {                              \
            if (_d < D1 || (_d == D1 && _e < I1)) {                          \
                if (_d < D0 || (_d == D0 && _e < I0)) {                      \
                    D2 = D1; I2 = I1; D1 = D0; I1 = I0; D0 = _d; I0 = _e;    \
                } else { D2 = D1; I2 = I1; D1 = _d; I1 = _e; }               \
            } else { D2 = _d; I2 = _e; }                                     \
        }                                                                    \
    } while (0)

// visit one bitmask row (z,y) under mask mk; direct-mapped cell lookups
#define PROW(zz, yy, mk)                                                     \
    do {                                                                     \
        ull rowm = *(const ull*)&sbm[((((zz) << 6) + (yy)) << 1)];           \
        rowm &= (mk);                                                        \
        while (rowm) {                                                       \
            int xb = __ffsll((long long)rowm) - 1;                           \
            rowm &= rowm - 1;                                                \
            int cell = (((((zz) << 6) + (yy)) << 6) + xb);                   \
            float4 qq = g_cell[hb + cell];                                   \
            int wi = __float_as_int(qq.w);                                   \
            int qi = wi & IDXM;                                              \
            float ddx = px - qq.x, ddy = py - qq.y, ddz = pz - qq.z;         \
            float dd = fmaf(ddx, ddx, fmaf(ddy, ddy, ddz * ddz));            \
            INS3(dd, qi);                                                    \
            if (wi & CHAINF) {                                               \
                int e = __float_as_int(g_qpos[qi].w);                        \
                while (e >= 0) {                                             \
                    float4 q2 = g_qpos[e];                                   \
                    float ex = px - q2.x, ey = py - q2.y, ez = pz - q2.z;    \
                    float d2c = fmaf(ex, ex, fmaf(ey, ey, ez * ez));         \
                    INS3(d2c, e);                                            \
                    e = __float_as_int(q2.w);                                \
                }                                                            \
            }                                                                \
        }                                                                    \
    } while (0)

// full scalar search (R11 logic) for rare window failures — bit-exact path
__device__ void scalar_point(const unsigned int* sbm, int hb, int b,
                             float px, float py, float pz,
                             const int* __restrict__ indices, int M, int pid) {
    int cx = cell_of(px);
    int cy = cell_of(py);
    int cz = cell_of(pz);

    float D0 = BIGF, D1 = BIGF, D2 = BIGF;
    int   I0 = 0,    I1 = 0,    I2 = 0;

    for (int r = 0; r <= 63; r++) {
        if (r > 0 && D2 < BIGF) {
            float br = ((float)r - 0.5f) * 0.05f;
            if (D2 + 1e-6f < br * br) break;
        }
        if (r == 0) {
            PROW(cz, cy, 1ull << cx);
            continue;
        }
        int xlo = max(cx - r, 0), xhi = min(cx + r, 63);
        ull fm = (xhi - xlo == 63) ? ~0ull
                                   : (((1ull << (xhi - xlo + 1)) - 1ull) << xlo);
        ull pm = 0ull;
        if (cx - r >= 0)  pm |= 1ull << (cx - r);
        if (cx + r <= 63) pm |= 1ull << (cx + r);

        int ylo = max(cy - r, 0), yhi = min(cy + r, 63);
        if (cz - r >= 0)  { int z = cz - r; for (int y = ylo; y <= yhi; y++) PROW(z, y, fm); }
        if (cz + r <= 63) { int z = cz + r; for (int y = ylo; y <= yhi; y++) PROW(z, y, fm); }
        int z0 = max(cz - r + 1, 0), z1 = min(cz + r - 1, 63);
        if (cy - r >= 0)  { int y = cy - r; for (int z = z0; z <= z1; z++) PROW(z, y, fm); }
        if (cy + r <= 63) { int y = cy + r; for (int z = z0; z <= z1; z++) PROW(z, y, fm); }
        if (pm) {
            int y0 = max(cy - r + 1, 0), y1 = min(cy + r - 1, 63);
            for (int z = z0; z <= z1; z++)
                for (int y = y0; y <= y1; y++) PROW(z, y, pm);
        }
    }

    if (D2 >= 1.0f) {   // cross-batch possible only here
        float pb = (float)b;
        D0 = BIGF; D1 = BIGF; D2 = BIGF; I0 = 0; I1 = 0; I2 = 0;
        for (int i = 0; i < M; i++) {
            int4 v = ((const int4*)indices)[i];
            float qb = (float)v.x;
            float qx = __fadd_rn(__fadd_rn(__fmul_rn((float)v.y, 0.05f), -1.6f), 0.025f);
            float qy = __fadd_rn(__fadd_rn(__fmul_rn((float)v.z, 0.05f), -1.6f), 0.025f);
            float qz = __fadd_rn(__fadd_rn(__fmul_rn((float)v.w, 0.05f), -1.6f), 0.025f);
            float dx = px - qx, dy = py - qy, dz = pz - qz, db = pb - qb;
            float dd = fmaf(dx, dx, fmaf(dy, dy, fmaf(dz, dz, db * db)));
            INS3(dd, i);
        }
    }

    float r0 = 1.0f / (D0 + 1e-8f);
    float r1 = 1.0f / (D1 + 1e-8f);
    float r2 = 1.0f / (D2 + 1e-8f);
    float s = r0 + r1 + r2;
    g_wv[pid] = make_float4(r0 / s, r1 / s, r2 / s, 0.0f);
    g_iw[pid] = make_int4(I0, I1, I2, 0);
}

__global__ void __launch_bounds__(TPB) nn_kernel(const float* __restrict__ pc,
                                                 const int* __restrict__ indices,
                                                 int M) {
    __shared__ unsigned int sbm[BMW];
    if (blockIdx.x >= g_nblk) return;

    int b  = g_dbatch[blockIdx.x];
    int pS = g_dstart[blockIdx.x];
    int pE = g_dend[blockIdx.x];
    int hb = b * CELLS;

    {
        const uint4* src = (const uint4*)&g_bm[b * BMW];
        uint4* dst = (uint4*)sbm;
        for (int i = threadIdx.x; i < BMW / 4; i += TPB) dst[i] = src[i];
    }
    __syncthreads();

    int ni = pS + threadIdx.x;
    if (ni >= pE) return;
    int pid = g_pid[ni];
    float px = pc[3 * pid], py = pc[3 * pid + 1], pz = pc[3 * pid + 2];

    int cx = cell_of(px);
    int cy = cell_of(py);
    int cz = cell_of(pz);

    // fixed +-WR x window (each row visited at most once)
    int xlo = max(cx - WR, 0), xhi = min(cx + WR, 63);
    ull fm = ((1ull << (xhi - xlo + 1)) - 1ull) << xlo;   // width <= 13

    float D0 = BIGF, D1 = BIGF, D2 = BIGF;
    int   I0 = 0,    I1 = 0,    I2 = 0;

    bool complete = false;

    // ring 0
    PROW(cz, cy, fm);

    // rings 1..WR over (dz,dy); per-row lower-bound prune
    for (int s = 1; s <= WR; s++) {
        float bs = ((float)s - 0.5f) * 0.05f;
        float bs2 = bs * bs;
        if (D2 + 1e-6f < bs2) { complete = true; break; }
        // rows dz = +-s, dy = -s..s
        for (int dy = -s; dy <= s; dy++) {
            float tb = fmaxf(fabsf((float)dy) - 0.5f, 0.0f) * 0.05f;
            float lb = fmaf(tb, tb, bs2);
            if (lb > D2 + 1e-6f) continue;
            int y = cy + dy;
            if ((unsigned)y > 63u) continue;
            int z = cz - s;
            if (z >= 0) PROW(z, y, fm);
            z = cz + s;
            if (z <= 63) PROW(z, y, fm);
        }
        // rows dy = +-s, dz = -s+1..s-1
        for (int dz = -s + 1; dz <= s - 1; dz++) {
            float tb = fmaxf(fabsf((float)dz) - 0.5f, 0.0f) * 0.05f;
            float lb = fmaf(tb, tb, bs2);
            if (lb > D2 + 1e-6f) continue;
            int z = cz + dz;
            if ((unsigned)z > 63u) continue;
            int y = cy - s;
            if (y >= 0) PROW(z, y, fm);
            y = cy + s;
            if (y <= 63) PROW(z, y, fm);
        }
    }
    // completeness: rings beyond WR and |dx| > WR both need D2+eps < (WR+0.5)^2*u^2
    if (!complete) complete = (D2 + 1e-6f < XBND2);

    if (complete) {
        float r0 = 1.0f / (D0 + 1e-8f);
        float r1 = 1.0f / (D1 + 1e-8f);
        float r2 = 1.0f / (D2 + 1e-8f);
        float s = r0 + r1 + r2;
        g_wv[pid] = make_float4(r0 / s, r1 / s, r2 / s, 0.0f);
        g_iw[pid] = make_int4(I0, I1, I2, 0);
    } else {
        scalar_point(sbm, hb, b, px, py, pz, indices, M, pid);
    }
}

// ---- weighted gather-interpolate: 8 threads/point, 2 float4 chains each ----
__global__ void interp_kernel(const float* __restrict__ feats,
                              float* __restrict__ out, int N, int C) {
    int t = blockIdx.x * blockDim.x + threadIdx.x;
    int n = t >> 3;
    int c = t & 7;
    if (n >= N) return;

    int4   iv = g_iw[n];
    float4 wv = g_wv[n];
    const float4* f = (const float4*)feats;
    int C4 = C >> 2;           // 16
    long ba = (long)iv.x * C4 + c;
    long bb = (long)iv.y * C4 + c;
    long bc = (long)iv.z * C4 + c;

    float4 a0 = f[ba],     b0 = f[bb],     c0 = f[bc];
    float4 a1 = f[ba + 8], b1 = f[bb + 8], c1 = f[bc + 8];

    float4 o0, o1;
    o0.x = wv.x * a0.x + wv.y * b0.x + wv.z * c0.x;
    o0.y = wv.x * a0.y + wv.y * b0.y + wv.z * c0.y;
    o0.z = wv.x * a0.z + wv.y * b0.z + wv.z * c0.z;
    o0.w = wv.x * a0.w + wv.y * b0.w + wv.z * c0.w;
    o1.x = wv.x * a1.x + wv.y * b1.x + wv.z * c1.x;
    o1.y = wv.x * a1.y + wv.y * b1.y + wv.z * c1.y;
    o1.z = wv.x * a1.z + wv.y * b1.z + wv.z * c1.z;
    o1.w = wv.x * a1.w + wv.y * b1.w + wv.z * c1.w;

    float4* ov = (float4*)out;
    ov[(long)n * C4 + c]     = o0;
    ov[(long)n * C4 + c + 8] = o1;
}

extern "C" void kernel_launch(void* const* d_in, const int* in_sizes, int n_in,
                              void* d_out, int out_size) {
    const float* features = (const float*)d_in[0];  // (M, C) f32
    const int*   indices  = (const int*)d_in[1];    // (M, 4) i32
    const float* pc       = (const float*)d_in[2];  // (N, 3) f32
    const int*   bids     = (const int*)d_in[3];    // (N,)   i32

    int M = in_sizes[1] / 4;
    int C = in_sizes[0] / M;
    int N = in_sizes[3];
    int mx = (M > N) ? M : N;

    k_init<<<1024, 256>>>();
    k_build_hist<<<(mx + 255) / 256, 256>>>(indices, M, pc, bids, N);
    k_part_compact<<<NPART + (M + 255) / 256, 256>>>(indices, M);
    k_off2<<<NPART, 256>>>();
    k_scatterp<<<(N + 255) / 256, 256>>>(pc, bids, N);

    int maxblk = (N + BPTS - 1) / BPTS + NB;
    nn_kernel<<<maxblk, TPB>>>(pc, indices, M);

    interp_kernel<<<(N * 8 + 255) / 256, 256>>>(features, (float*)d_out, N, C);
}